// round 13
// baseline (speedup 1.0000x reference)
#include <cuda_runtime.h>
#include <cuda_bf16.h>
#include <math.h>
#include <stdint.h>

#define D_MODEL 1024
#define D_FF    4096
#define NUM_E   24
#define TOKENS  2048
#define CAP     512

#define BM 256
#define BN 64
#define BK 64
#define NPERS 296   // persistent CTAs: 2 per SM x 148

// smem plan (dynamic, 112 KB): A 3x32KB | Bb(bf16) 2x8KB
#define OFF_A   0
#define OFF_BB  98304
#define SMEM_DYN 114688

// ---------------- scratch ----------------
__device__ int   g_cnt[NUM_E];
__device__ int   g_perm[NUM_E * CAP];
__device__ int   g_slot[TOKENS * 2];
__device__ float g_wgt[TOKENS * 2];
__device__ __nv_bfloat16 g_xb[(size_t)TOKENS * D_MODEL];
__device__ __nv_bfloat16 g_h[(size_t)NUM_E * CAP * D_FF];
__device__ float g_y[(size_t)NUM_E * CAP * D_MODEL];

// ---------------- helpers ----------------
__device__ __forceinline__ uint32_t smem_u32(const void* p) {
    uint32_t a;
    asm("{ .reg .u64 t; cvta.to.shared.u64 t, %1; cvt.u32.u64 %0, t; }" : "=r"(a) : "l"(p));
    return a;
}
#define SW128_(o) ((o) ^ (((o) >> 3) & 0x70))

__device__ __forceinline__ uint32_t pk2(float a, float b) {
    __nv_bfloat162 h = __floats2bfloat162_rn(a, b);
    return *reinterpret_cast<uint32_t*>(&h);
}
__device__ __forceinline__ float fast_gelu(float v) {
    float u  = v * (0.7978845608f + 0.0356774081f * v * v);
    float ez = __expf(2.f * u);
    float t  = 1.f - __fdividef(2.f, 1.f + ez);
    return 0.5f * v * (1.f + t);
}
__device__ __forceinline__ void mma16816(float* d, const uint32_t* a, uint32_t b0, uint32_t b1) {
    asm volatile(
        "mma.sync.aligned.m16n8k16.row.col.f32.bf16.bf16.f32 "
        "{%0,%1,%2,%3},{%4,%5,%6,%7},{%8,%9},{%0,%1,%2,%3};\n"
        : "+f"(d[0]), "+f"(d[1]), "+f"(d[2]), "+f"(d[3])
        : "r"(a[0]), "r"(a[1]), "r"(a[2]), "r"(a[3]), "r"(b0), "r"(b1));
}
__device__ __forceinline__ void ldmA(uint32_t* r, uint32_t addr) {
    asm volatile("ldmatrix.sync.aligned.m8n8.x4.shared.b16 {%0,%1,%2,%3},[%4];"
        : "=r"(r[0]), "=r"(r[1]), "=r"(r[2]), "=r"(r[3]) : "r"(addr));
}
__device__ __forceinline__ void ldmBT(uint32_t* r, uint32_t addr) {
    asm volatile("ldmatrix.sync.aligned.m8n8.x4.trans.shared.b16 {%0,%1,%2,%3},[%4];"
        : "=r"(r[0]), "=r"(r[1]), "=r"(r[2]), "=r"(r[3]) : "r"(addr));
}
#define CP_ASYNC16(dst, src) \
    asm volatile("cp.async.cg.shared.global [%0],[%1],16;" :: "r"(dst), "l"(src) : "memory")
#define CP_COMMIT()  asm volatile("cp.async.commit_group;" ::: "memory")
__device__ __forceinline__ void cp_wait1() { asm volatile("cp.async.wait_group 1;" ::: "memory"); }
__device__ __forceinline__ void cp_wait0() { asm volatile("cp.async.wait_group 0;" ::: "memory"); }

// ---------------- small kernels ----------------
__global__ void zero_cnt_kernel() { if (threadIdx.x < NUM_E) g_cnt[threadIdx.x] = 0; }

__global__ void gate_kernel(const float* __restrict__ x,
                            const float* __restrict__ gw,
                            const float* __restrict__ gb) {
    __shared__ float sx[D_MODEL];
    __shared__ float sc[NUM_E];
    const int t = blockIdx.x;
    const float* xr = x + (size_t)t * D_MODEL;
    for (int i = threadIdx.x; i < D_MODEL; i += blockDim.x) sx[i] = xr[i];
    __syncthreads();
    for (int i = threadIdx.x; i < D_MODEL; i += blockDim.x)
        g_xb[(size_t)t * D_MODEL + i] = __float2bfloat16(sx[i]);

    const int lane = threadIdx.x & 31, warp = threadIdx.x >> 5;
    for (int e = warp; e < NUM_E; e += 4) {
        float s = 0.f;
        for (int d = lane; d < D_MODEL; d += 32) s += sx[d] * gw[d * NUM_E + e];
        #pragma unroll
        for (int o = 16; o; o >>= 1) s += __shfl_xor_sync(0xffffffffu, s, o);
        if (lane == 0) sc[e] = s + gb[e];
    }
    __syncthreads();
    if (threadIdx.x == 0) {
        int i0 = 0; float v0 = sc[0];
        for (int e = 1; e < NUM_E; e++) if (sc[e] > v0) { v0 = sc[e]; i0 = e; }
        int i1 = -1; float v1 = -3.4e38f;
        for (int e = 0; e < NUM_E; e++) if (e != i0 && sc[e] > v1) { v1 = sc[e]; i1 = e; }
        float w0 = 1.f / (1.f + expf(v1 - v0));
        int ev[2] = { i0, i1 };
        float wv[2] = { w0, 1.f - w0 };
        #pragma unroll
        for (int k = 0; k < 2; k++) {
            int e = ev[k];
            int p = atomicAdd(&g_cnt[e], 1);
            if (p < CAP) { g_perm[e*CAP+p] = t; g_slot[t*2+k] = e*CAP+p; g_wgt[t*2+k] = wv[k]; }
            else         { g_slot[t*2+k] = -1; g_wgt[t*2+k] = 0.f; }
        }
    }
}

// ---------------- persistent bf16 grouped GEMM: 256x64 tile, BK=64, 3-stage A ----------------
template<int KD, int ND, bool GATHER, bool GELU_ACT>
__global__ __launch_bounds__(256, 2)
void moe_gemm(const float* __restrict__ W,      // [E, KD, ND] fp32
              const float* __restrict__ bias) { // [E, ND]
    extern __shared__ __align__(1024) char smem[];
    const uint32_t sb = smem_u32(smem);
    const int tid = threadIdx.x, lane = tid & 31, wid = tid >> 5;
    const int warpM = wid >> 1, warpN = wid & 1;

    constexpr int NT_N = ND / BN;
    constexpr int NT_M = CAP / BM;               // 2
    constexpr int NT   = NUM_E * NT_M * NT_N;
    constexpr int NS   = KD / BK;

    for (int tile = blockIdx.x; tile < NT; tile += NPERS) {
        const int e  = tile / (NT_M * NT_N);
        const int r_ = tile % (NT_M * NT_N);
        const int m0 = (r_ / NT_N) * BM;
        const int n0 = (r_ % NT_N) * BN;
        const int cnt = min(g_cnt[e], CAP);
        if (m0 >= cnt) continue;

        // ---- A loader: 4 threads/row (32B each), 4 passes of 64 rows ----
        const char* agp[4];
        uint32_t dA0[4], dA1[4];
        #pragma unroll
        for (int p = 0; p < 4; p++) {
            const int rloc = p * 64 + (tid >> 2);
            const int m = m0 + rloc;
            const __nv_bfloat16* rowp;
            if (GATHER) {
                int tok = (m < cnt) ? g_perm[e * CAP + m] : g_perm[e * CAP];
                rowp = g_xb + (size_t)tok * KD;
            } else {
                rowp = g_h + ((size_t)e * CAP + m) * KD;
            }
            agp[p] = (const char*)rowp + (tid & 3) * 32;
            dA0[p] = SW128_((uint32_t)(rloc * 128 + (tid & 3) * 32));
            dA1[p] = SW128_((uint32_t)(rloc * 128 + (tid & 3) * 32 + 16));
        }
        // ---- B loader: kr = tid>>2 (64 k-rows, 4 thr/row), 16 floats each ----
        const int kr = tid >> 2, ns = tid & 3;
        const float* bsrc = W + ((size_t)e * KD + kr) * ND + n0 + ns * 16;
        const uint32_t dB0 = SW128_((uint32_t)(kr * 128 + ns * 32));
        const uint32_t dB1 = SW128_((uint32_t)(kr * 128 + ns * 32 + 16));

        float acc[4][4][4];
        #pragma unroll
        for (int i = 0; i < 4; i++)
            #pragma unroll
            for (int j = 0; j < 4; j++)
                #pragma unroll
                for (int q = 0; q < 4; q++) acc[i][j][q] = 0.f;

        float4 rb[4];
        auto cpA = [&](int s) {
            const uint32_t aB = sb + OFF_A + (s % 3) * 32768;
            #pragma unroll
            for (int p = 0; p < 4; p++) {
                CP_ASYNC16(aB + dA0[p], agp[p] + s * 128);
                CP_ASYNC16(aB + dA1[p], agp[p] + s * 128 + 16);
            }
            CP_COMMIT();
        };
        auto ldgB = [&](int s) {
            const float* p = bsrc + (size_t)s * BK * ND;
            #pragma unroll
            for (int j = 0; j < 4; j++)
                rb[j] = *reinterpret_cast<const float4*>(p + 4 * j);
        };
        auto stsB = [&](int s) {
            char* bb = smem + OFF_BB + (s & 1) * 8192;
            *reinterpret_cast<uint4*>(bb + dB0) =
                make_uint4(pk2(rb[0].x, rb[0].y), pk2(rb[0].z, rb[0].w),
                           pk2(rb[1].x, rb[1].y), pk2(rb[1].z, rb[1].w));
            *reinterpret_cast<uint4*>(bb + dB1) =
                make_uint4(pk2(rb[2].x, rb[2].y), pk2(rb[2].z, rb[2].w),
                           pk2(rb[3].x, rb[3].y), pk2(rb[3].z, rb[3].w));
        };
        auto compute = [&](int s) {
            const uint32_t aB = sb + OFF_A  + (s % 3) * 32768;
            const uint32_t bB = sb + OFF_BB + (s & 1) * 8192;
            #pragma unroll
            for (int kk = 0; kk < 4; kk++) {
                uint32_t af[4][4], bfr[2][4];
                #pragma unroll
                for (int mf = 0; mf < 4; mf++) {
                    int row = warpM * 64 + mf * 16 + (lane & 15);
                    int seg = kk * 2 + (lane >> 4);
                    ldmA(af[mf], aB + SW128_(row * 128 + seg * 16));
                }
                #pragma unroll
                for (int np = 0; np < 2; np++) {
                    int krow = kk * 16 + (lane & 15);
                    int nc   = warpN * 32 + np * 16 + ((lane >> 4) & 1) * 8;
                    ldmBT(bfr[np], bB + SW128_(krow * 128 + nc * 2));
                }
                #pragma unroll
                for (int mf = 0; mf < 4; mf++)
                    #pragma unroll
                    for (int nf = 0; nf < 4; nf++)
                        mma16816(acc[mf][nf], af[mf],
                                 bfr[nf >> 1][(nf & 1) * 2], bfr[nf >> 1][(nf & 1) * 2 + 1]);
            }
        };

        // prologue
        cpA(0); cpA(1);
        ldgB(0);
        cp_wait1();          // stage 0 landed
        stsB(0);
        __syncthreads();

        for (int s = 0; s < NS; s++) {
            if (s + 2 < NS) cpA(s + 2);
            if (s + 1 < NS) ldgB(s + 1);
            compute(s);
            if (s + 1 < NS) stsB(s + 1);
            if      (s + 2 < NS) cp_wait1();
            else if (s + 1 < NS) cp_wait0();
            __syncthreads();
        }

        // ---- epilogue ----
        const int grp = lane >> 2, tig = lane & 3;
        #pragma unroll
        for (int mf = 0; mf < 4; mf++) {
            const int r0 = m0 + warpM * 64 + mf * 16 + grp;
            #pragma unroll
            for (int nf = 0; nf < 4; nf++) {
                const int col = n0 + warpN * 32 + nf * 8 + 2 * tig;
                const float bv0 = __ldg(&bias[e * ND + col]);
                const float bv1 = __ldg(&bias[e * ND + col + 1]);
                #pragma unroll
                for (int h = 0; h < 2; h++) {
                    const int row = r0 + 8 * h;
                    float v0 = acc[mf][nf][2 * h + 0] + bv0;
                    float v1 = acc[mf][nf][2 * h + 1] + bv1;
                    if (GELU_ACT) {
                        v0 = fast_gelu(v0);
                        v1 = fast_gelu(v1);
                        *reinterpret_cast<uint32_t*>(
                            g_h + ((size_t)e * CAP + row) * ND + col) = pk2(v0, v1);
                    } else {
                        *reinterpret_cast<float2*>(
                            g_y + ((size_t)e * CAP + row) * ND + col) = make_float2(v0, v1);
                    }
                }
            }
        }
    }
}

// out[t] = x[t] + w0*y[slot0] + w1*y[slot1]
__global__ void combine_kernel(const float* __restrict__ x, float* __restrict__ out) {
    const int t = blockIdx.x;
    const int s0 = g_slot[t * 2], s1 = g_slot[t * 2 + 1];
    const float w0 = g_wgt[t * 2], w1 = g_wgt[t * 2 + 1];
    const float4* xr = reinterpret_cast<const float4*>(x + (size_t)t * D_MODEL);
    float4* orw = reinterpret_cast<float4*>(out + (size_t)t * D_MODEL);
    const float4* y0 = (s0 >= 0) ? reinterpret_cast<const float4*>(g_y + (size_t)s0 * D_MODEL) : nullptr;
    const float4* y1 = (s1 >= 0) ? reinterpret_cast<const float4*>(g_y + (size_t)s1 * D_MODEL) : nullptr;
    const int i = threadIdx.x;
    float4 rv = xr[i];
    if (y0) { float4 a = y0[i]; rv.x += w0 * a.x; rv.y += w0 * a.y; rv.z += w0 * a.z; rv.w += w0 * a.w; }
    if (y1) { float4 a = y1[i]; rv.x += w1 * a.x; rv.y += w1 * a.y; rv.z += w1 * a.z; rv.w += w1 * a.w; }
    orw[i] = rv;
}

// ---------------- launch ----------------
extern "C" void kernel_launch(void* const* d_in, const int* in_sizes, int n_in,
                              void* d_out, int out_size) {
    const float* x  = (const float*)d_in[0];
    const float* gw = (const float*)d_in[1];
    const float* gb = (const float*)d_in[2];
    const float* w1 = (const float*)d_in[3];
    const float* b1 = (const float*)d_in[4];
    const float* w2 = (const float*)d_in[5];
    const float* b2 = (const float*)d_in[6];
    float* out = (float*)d_out;

    cudaFuncSetAttribute(moe_gemm<D_MODEL, D_FF, true,  true >,
                         cudaFuncAttributeMaxDynamicSharedMemorySize, SMEM_DYN);
    cudaFuncSetAttribute(moe_gemm<D_FF, D_MODEL, false, false>,
                         cudaFuncAttributeMaxDynamicSharedMemorySize, SMEM_DYN);

    zero_cnt_kernel<<<1, 32>>>();
    gate_kernel<<<TOKENS, 128>>>(x, gw, gb);

    moe_gemm<D_MODEL, D_FF, true,  true ><<<NPERS, 256, SMEM_DYN>>>(w1, b1);
    moe_gemm<D_FF, D_MODEL, false, false><<<NPERS, 256, SMEM_DYN>>>(w2, b2);

    combine_kernel<<<TOKENS, 256>>>(x, out);
}

// round 14
// speedup vs baseline: 1.2066x; 1.2066x over previous
#include <cuda_runtime.h>
#include <cuda_bf16.h>
#include <math.h>
#include <stdint.h>

#define D_MODEL 1024
#define D_FF    4096
#define NUM_E   24
#define TOKENS  2048
#define CAP     512

#define BM 256
#define BN 64
#define BK 32

// smem plan (dynamic, 112 KB): A 4x16KB | Bf(fp32) 4x8KB | Bb(bf16) 4x4KB
#define OFF_A   0
#define OFF_BF  65536
#define OFF_BB  98304
#define SMEM_DYN 114688

// ---------------- scratch ----------------
__device__ int   g_cnt[NUM_E];
__device__ int   g_perm[NUM_E * CAP];
__device__ int   g_slot[TOKENS * 2];
__device__ float g_wgt[TOKENS * 2];
__device__ __nv_bfloat16 g_xb[(size_t)TOKENS * D_MODEL];
__device__ __nv_bfloat16 g_h[(size_t)NUM_E * CAP * D_FF];
__device__ float g_y[(size_t)NUM_E * CAP * D_MODEL];

// ---------------- helpers ----------------
__device__ __forceinline__ uint32_t smem_u32(const void* p) {
    uint32_t a;
    asm("{ .reg .u64 t; cvta.to.shared.u64 t, %1; cvt.u32.u64 %0, t; }" : "=r"(a) : "l"(p));
    return a;
}
#define SW128_(o) ((o) ^ (((o) >> 3) & 0x70))
#define SW64_(o)  ((o) ^ (((o) >> 3) & 0x30))

__device__ __forceinline__ uint32_t pk2(float a, float b) {
    __nv_bfloat162 h = __floats2bfloat162_rn(a, b);
    return *reinterpret_cast<uint32_t*>(&h);
}
__device__ __forceinline__ float fast_gelu(float v) {
    float u  = v * (0.7978845608f + 0.0356774081f * v * v);
    float ez = __expf(2.f * u);
    float t  = 1.f - __fdividef(2.f, 1.f + ez);
    return 0.5f * v * (1.f + t);
}
__device__ __forceinline__ void mma16816(float* d, const uint32_t* a, uint32_t b0, uint32_t b1) {
    asm volatile(
        "mma.sync.aligned.m16n8k16.row.col.f32.bf16.bf16.f32 "
        "{%0,%1,%2,%3},{%4,%5,%6,%7},{%8,%9},{%0,%1,%2,%3};\n"
        : "+f"(d[0]), "+f"(d[1]), "+f"(d[2]), "+f"(d[3])
        : "r"(a[0]), "r"(a[1]), "r"(a[2]), "r"(a[3]), "r"(b0), "r"(b1));
}
__device__ __forceinline__ void ldmA(uint32_t* r, uint32_t addr) {
    asm volatile("ldmatrix.sync.aligned.m8n8.x4.shared.b16 {%0,%1,%2,%3},[%4];"
        : "=r"(r[0]), "=r"(r[1]), "=r"(r[2]), "=r"(r[3]) : "r"(addr));
}
__device__ __forceinline__ void ldmBT(uint32_t* r, uint32_t addr) {
    asm volatile("ldmatrix.sync.aligned.m8n8.x4.trans.shared.b16 {%0,%1,%2,%3},[%4];"
        : "=r"(r[0]), "=r"(r[1]), "=r"(r[2]), "=r"(r[3]) : "r"(addr));
}
#define CP_ASYNC16(dst, src) \
    asm volatile("cp.async.cg.shared.global [%0],[%1],16;" :: "r"(dst), "l"(src) : "memory")
#define CP_COMMIT()  asm volatile("cp.async.commit_group;" ::: "memory")
__device__ __forceinline__ void cp_wait0() { asm volatile("cp.async.wait_group 0;" ::: "memory"); }

// ---------------- small kernels ----------------
__global__ void zero_cnt_kernel() { if (threadIdx.x < NUM_E) g_cnt[threadIdx.x] = 0; }

__global__ void gate_kernel(const float* __restrict__ x,
                            const float* __restrict__ gw,
                            const float* __restrict__ gb) {
    __shared__ float sx[D_MODEL];
    __shared__ float sc[NUM_E];
    const int t = blockIdx.x;
    const float* xr = x + (size_t)t * D_MODEL;
    for (int i = threadIdx.x; i < D_MODEL; i += blockDim.x) sx[i] = xr[i];
    __syncthreads();
    for (int i = threadIdx.x; i < D_MODEL; i += blockDim.x)
        g_xb[(size_t)t * D_MODEL + i] = __float2bfloat16(sx[i]);

    const int lane = threadIdx.x & 31, warp = threadIdx.x >> 5;
    for (int e = warp; e < NUM_E; e += 4) {
        float s = 0.f;
        for (int d = lane; d < D_MODEL; d += 32) s += sx[d] * gw[d * NUM_E + e];
        #pragma unroll
        for (int o = 16; o; o >>= 1) s += __shfl_xor_sync(0xffffffffu, s, o);
        if (lane == 0) sc[e] = s + gb[e];
    }
    __syncthreads();
    if (threadIdx.x == 0) {
        int i0 = 0; float v0 = sc[0];
        for (int e = 1; e < NUM_E; e++) if (sc[e] > v0) { v0 = sc[e]; i0 = e; }
        int i1 = -1; float v1 = -3.4e38f;
        for (int e = 0; e < NUM_E; e++) if (e != i0 && sc[e] > v1) { v1 = sc[e]; i1 = e; }
        float w0 = 1.f / (1.f + expf(v1 - v0));
        int ev[2] = { i0, i1 };
        float wv[2] = { w0, 1.f - w0 };
        #pragma unroll
        for (int k = 0; k < 2; k++) {
            int e = ev[k];
            int p = atomicAdd(&g_cnt[e], 1);
            if (p < CAP) { g_perm[e*CAP+p] = t; g_slot[t*2+k] = e*CAP+p; g_wgt[t*2+k] = wv[k]; }
            else         { g_slot[t*2+k] = -1; g_wgt[t*2+k] = 0.f; }
        }
    }
}

// ---------------- bf16 grouped GEMM: 256x64 tile, BK=32, paired stages (1 barrier / 2 stages) ----
template<int KD, int ND, bool GATHER, bool GELU_ACT>
__global__ __launch_bounds__(256)
void moe_gemm(const float* __restrict__ W,      // [E, KD, ND] fp32
              const float* __restrict__ bias) { // [E, ND]
    const int e   = blockIdx.z;
    const int cnt = min(g_cnt[e], CAP);
    const int m0  = blockIdx.y * BM;
    if (m0 >= cnt) return;
    const int n0  = blockIdx.x * BN;

    extern __shared__ __align__(1024) char smem[];
    const uint32_t sb = smem_u32(smem);
    const int tid = threadIdx.x, lane = tid & 31, wid = tid >> 5;
    const int warpM = wid >> 1, warpN = wid & 1;

    // ---- A loader: 4 threads/row (16B each), 4 passes of 64 rows ----
    const char* agp[4];
    uint32_t dstA[4];
    #pragma unroll
    for (int p = 0; p < 4; p++) {
        const int rloc = p * 64 + (tid >> 2);
        const int m = m0 + rloc;
        const __nv_bfloat16* rowp;
        if (GATHER) {
            int tok = (m < cnt) ? g_perm[e * CAP + m] : g_perm[e * CAP];
            rowp = g_xb + (size_t)tok * KD;
        } else {
            rowp = g_h + ((size_t)e * CAP + m) * KD;
        }
        agp[p]  = (const char*)rowp + (tid & 3) * 16;
        dstA[p] = SW64_((uint32_t)(rloc * 64 + (tid & 3) * 16));
    }
    // ---- B loader: kr = tid>>3 (32 k-rows, 8 thr/row), 8 floats each ----
    const int kr = tid >> 3, ns = tid & 7;
    const float* bsrc = W + ((size_t)e * KD + kr) * ND + n0 + ns * 8;
    const uint32_t dstBF = (uint32_t)(kr * 256 + ns * 32);
    const uint32_t dstBB = SW128_((uint32_t)(kr * 128 + ns * 16));

    float acc[4][4][4];
    #pragma unroll
    for (int i = 0; i < 4; i++)
        #pragma unroll
        for (int j = 0; j < 4; j++)
            #pragma unroll
            for (int q = 0; q < 4; q++) acc[i][j][q] = 0.f;

    auto cpStage = [&](int s) {
        const int b = s & 3;
        const uint32_t aB = sb + OFF_A + b * 16384;
        #pragma unroll
        for (int p = 0; p < 4; p++)
            CP_ASYNC16(aB + dstA[p], agp[p] + s * 64);
        const uint32_t bf = sb + OFF_BF + b * 8192 + dstBF;
        const char* src = (const char*)(bsrc + (size_t)s * BK * ND);
        CP_ASYNC16(bf,      src);
        CP_ASYNC16(bf + 16, src + 16);
    };
    auto convB = [&](int s) {   // convert OWN cp'd fp32 bytes -> bf16 tile
        const float4* f = reinterpret_cast<const float4*>(smem + OFF_BF + (s & 3) * 8192 + dstBF);
        float4 f0 = f[0], f1 = f[1];
        uint4 v = make_uint4(pk2(f0.x, f0.y), pk2(f0.z, f0.w),
                             pk2(f1.x, f1.y), pk2(f1.z, f1.w));
        *reinterpret_cast<uint4*>(smem + OFF_BB + (s & 3) * 4096 + dstBB) = v;
    };
    auto compute = [&](int s) {
        const uint32_t aB = sb + OFF_A  + (s & 3) * 16384;
        const uint32_t bB = sb + OFF_BB + (s & 3) * 4096;
        #pragma unroll
        for (int kk = 0; kk < 2; kk++) {
            uint32_t af[4][4], bfr[2][4];
            #pragma unroll
            for (int mf = 0; mf < 4; mf++) {
                int row = warpM * 64 + mf * 16 + (lane & 15);
                int seg = kk * 2 + (lane >> 4);
                ldmA(af[mf], aB + SW64_(row * 64 + seg * 16));
            }
            #pragma unroll
            for (int np = 0; np < 2; np++) {
                int krow = kk * 16 + (lane & 15);
                int nc   = warpN * 32 + np * 16 + ((lane >> 4) & 1) * 8;
                ldmBT(bfr[np], bB + SW128_(krow * 128 + nc * 2));
            }
            #pragma unroll
            for (int mf = 0; mf < 4; mf++)
                #pragma unroll
                for (int nf = 0; nf < 4; nf++)
                    mma16816(acc[mf][nf], af[mf],
                             bfr[nf >> 1][(nf & 1) * 2], bfr[nf >> 1][(nf & 1) * 2 + 1]);
        }
    };

    const int NS = KD / BK;     // 32 or 128, always even
    // prologue: pair (0,1) in flight
    cpStage(0); cpStage(1); CP_COMMIT();

    for (int s = 0; s < NS; s += 2) {
        cp_wait0();             // pair (s, s+1) landed
        convB(s);
        convB(s + 1);
        __syncthreads();        // Bb visible; A slots (s+2)&3,(s+3)&3 free (held s-2,s-1)
        if (s + 2 < NS) { cpStage(s + 2); cpStage(s + 3); CP_COMMIT(); }
        compute(s);
        compute(s + 1);
    }

    // ---- epilogue ----
    const int grp = lane >> 2, tig = lane & 3;
    #pragma unroll
    for (int mf = 0; mf < 4; mf++) {
        const int r0 = m0 + warpM * 64 + mf * 16 + grp;
        #pragma unroll
        for (int nf = 0; nf < 4; nf++) {
            const int col = n0 + warpN * 32 + nf * 8 + 2 * tig;
            const float bv0 = __ldg(&bias[e * ND + col]);
            const float bv1 = __ldg(&bias[e * ND + col + 1]);
            #pragma unroll
            for (int h = 0; h < 2; h++) {
                const int row = r0 + 8 * h;
                float v0 = acc[mf][nf][2 * h + 0] + bv0;
                float v1 = acc[mf][nf][2 * h + 1] + bv1;
                if (GELU_ACT) {
                    v0 = fast_gelu(v0);
                    v1 = fast_gelu(v1);
                    *reinterpret_cast<uint32_t*>(
                        g_h + ((size_t)e * CAP + row) * ND + col) = pk2(v0, v1);
                } else {
                    *reinterpret_cast<float2*>(
                        g_y + ((size_t)e * CAP + row) * ND + col) = make_float2(v0, v1);
                }
            }
        }
    }
}

// out[t] = x[t] + w0*y[slot0] + w1*y[slot1]
__global__ void combine_kernel(const float* __restrict__ x, float* __restrict__ out) {
    const int t = blockIdx.x;
    const int s0 = g_slot[t * 2], s1 = g_slot[t * 2 + 1];
    const float w0 = g_wgt[t * 2], w1 = g_wgt[t * 2 + 1];
    const float4* xr = reinterpret_cast<const float4*>(x + (size_t)t * D_MODEL);
    float4* orw = reinterpret_cast<float4*>(out + (size_t)t * D_MODEL);
    const float4* y0 = (s0 >= 0) ? reinterpret_cast<const float4*>(g_y + (size_t)s0 * D_MODEL) : nullptr;
    const float4* y1 = (s1 >= 0) ? reinterpret_cast<const float4*>(g_y + (size_t)s1 * D_MODEL) : nullptr;
    const int i = threadIdx.x;
    float4 rv = xr[i];
    if (y0) { float4 a = y0[i]; rv.x += w0 * a.x; rv.y += w0 * a.y; rv.z += w0 * a.z; rv.w += w0 * a.w; }
    if (y1) { float4 a = y1[i]; rv.x += w1 * a.x; rv.y += w1 * a.y; rv.z += w1 * a.z; rv.w += w1 * a.w; }
    orw[i] = rv;
}

// ---------------- launch ----------------
extern "C" void kernel_launch(void* const* d_in, const int* in_sizes, int n_in,
                              void* d_out, int out_size) {
    const float* x  = (const float*)d_in[0];
    const float* gw = (const float*)d_in[1];
    const float* gb = (const float*)d_in[2];
    const float* w1 = (const float*)d_in[3];
    const float* b1 = (const float*)d_in[4];
    const float* w2 = (const float*)d_in[5];
    const float* b2 = (const float*)d_in[6];
    float* out = (float*)d_out;

    cudaFuncSetAttribute(moe_gemm<D_MODEL, D_FF, true,  true >,
                         cudaFuncAttributeMaxDynamicSharedMemorySize, SMEM_DYN);
    cudaFuncSetAttribute(moe_gemm<D_FF, D_MODEL, false, false>,
                         cudaFuncAttributeMaxDynamicSharedMemorySize, SMEM_DYN);

    zero_cnt_kernel<<<1, 32>>>();
    gate_kernel<<<TOKENS, 128>>>(x, gw, gb);

    dim3 g1(D_FF / BN, CAP / BM, NUM_E);      // (64, 2, 24)
    moe_gemm<D_MODEL, D_FF, true,  true ><<<g1, 256, SMEM_DYN>>>(w1, b1);

    dim3 g2(D_MODEL / BN, CAP / BM, NUM_E);   // (16, 2, 24)
    moe_gemm<D_FF, D_MODEL, false, false><<<g2, 256, SMEM_DYN>>>(w2, b2);

    combine_kernel<<<TOKENS, 256>>>(x, out);
}

// round 15
// speedup vs baseline: 1.2126x; 1.0050x over previous
#include <cuda_runtime.h>
#include <cuda_bf16.h>
#include <math.h>
#include <stdint.h>

#define D_MODEL 1024
#define D_FF    4096
#define NUM_E   24
#define TOKENS  2048
#define CAP     512

#define BM 256
#define BN 64
#define BK 32
#define NPERS 296

#define NT1 (NUM_E * 2 * 64)          // 3072 GEMM1 tiles (2 m-tiles x 64 n-tiles x 24)
#define NT2 (NUM_E * 2 * 16)          // 768  GEMM2 tiles
#define NTT (NT1 + NT2)
#define DONE_TARGET 128               // per-expert GEMM1 tiles

// smem plan (dynamic, 112 KB): A 4x16KB | Bf(fp32) 4x8KB | Bb(bf16) 4x4KB
#define OFF_A   0
#define OFF_BF  65536
#define OFF_BB  98304
#define SMEM_DYN 114688

// ---------------- scratch ----------------
__device__ int   g_cnt[NUM_E];
__device__ int   g_done[NUM_E];
__device__ int   g_ticket;
__device__ int   g_perm[NUM_E * CAP];
__device__ int   g_slot[TOKENS * 2];
__device__ float g_wgt[TOKENS * 2];
__device__ __nv_bfloat16 g_xb[(size_t)TOKENS * D_MODEL];
__device__ __nv_bfloat16 g_h[(size_t)NUM_E * CAP * D_FF];
__device__ float g_y[(size_t)NUM_E * CAP * D_MODEL];

// ---------------- helpers ----------------
__device__ __forceinline__ uint32_t smem_u32(const void* p) {
    uint32_t a;
    asm("{ .reg .u64 t; cvta.to.shared.u64 t, %1; cvt.u32.u64 %0, t; }" : "=r"(a) : "l"(p));
    return a;
}
#define SW128_(o) ((o) ^ (((o) >> 3) & 0x70))
#define SW64_(o)  ((o) ^ (((o) >> 3) & 0x30))

__device__ __forceinline__ int ld_acq(const int* p) {
    int v;
    asm volatile("ld.acquire.gpu.s32 %0, [%1];" : "=r"(v) : "l"(p) : "memory");
    return v;
}
__device__ __forceinline__ uint32_t pk2(float a, float b) {
    __nv_bfloat162 h = __floats2bfloat162_rn(a, b);
    return *reinterpret_cast<uint32_t*>(&h);
}
__device__ __forceinline__ float fast_gelu(float v) {
    float u  = v * (0.7978845608f + 0.0356774081f * v * v);
    float ez = __expf(2.f * u);
    float t  = 1.f - __fdividef(2.f, 1.f + ez);
    return 0.5f * v * (1.f + t);
}
__device__ __forceinline__ void mma16816(float* d, const uint32_t* a, uint32_t b0, uint32_t b1) {
    asm volatile(
        "mma.sync.aligned.m16n8k16.row.col.f32.bf16.bf16.f32 "
        "{%0,%1,%2,%3},{%4,%5,%6,%7},{%8,%9},{%0,%1,%2,%3};\n"
        : "+f"(d[0]), "+f"(d[1]), "+f"(d[2]), "+f"(d[3])
        : "r"(a[0]), "r"(a[1]), "r"(a[2]), "r"(a[3]), "r"(b0), "r"(b1));
}
__device__ __forceinline__ void ldmA(uint32_t* r, uint32_t addr) {
    asm volatile("ldmatrix.sync.aligned.m8n8.x4.shared.b16 {%0,%1,%2,%3},[%4];"
        : "=r"(r[0]), "=r"(r[1]), "=r"(r[2]), "=r"(r[3]) : "r"(addr));
}
__device__ __forceinline__ void ldmBT(uint32_t* r, uint32_t addr) {
    asm volatile("ldmatrix.sync.aligned.m8n8.x4.trans.shared.b16 {%0,%1,%2,%3},[%4];"
        : "=r"(r[0]), "=r"(r[1]), "=r"(r[2]), "=r"(r[3]) : "r"(addr));
}
#define CP_ASYNC16(dst, src) \
    asm volatile("cp.async.cg.shared.global [%0],[%1],16;" :: "r"(dst), "l"(src) : "memory")
#define CP_COMMIT()  asm volatile("cp.async.commit_group;" ::: "memory")
__device__ __forceinline__ void cp_wait0() { asm volatile("cp.async.wait_group 0;" ::: "memory"); }

// ---------------- small kernels ----------------
__global__ void zero_kernel() {
    if (threadIdx.x < NUM_E) { g_cnt[threadIdx.x] = 0; g_done[threadIdx.x] = 0; }
    if (threadIdx.x == 31) g_ticket = 0;
}

__global__ void gate_kernel(const float* __restrict__ x,
                            const float* __restrict__ gw,
                            const float* __restrict__ gb) {
    __shared__ float sx[D_MODEL];
    __shared__ float sc[NUM_E];
    const int t = blockIdx.x;
    const float* xr = x + (size_t)t * D_MODEL;
    for (int i = threadIdx.x; i < D_MODEL; i += blockDim.x) sx[i] = xr[i];
    __syncthreads();
    for (int i = threadIdx.x; i < D_MODEL; i += blockDim.x)
        g_xb[(size_t)t * D_MODEL + i] = __float2bfloat16(sx[i]);

    const int lane = threadIdx.x & 31, warp = threadIdx.x >> 5;
    for (int e = warp; e < NUM_E; e += 4) {
        float s = 0.f;
        for (int d = lane; d < D_MODEL; d += 32) s += sx[d] * gw[d * NUM_E + e];
        #pragma unroll
        for (int o = 16; o; o >>= 1) s += __shfl_xor_sync(0xffffffffu, s, o);
        if (lane == 0) sc[e] = s + gb[e];
    }
    __syncthreads();
    if (threadIdx.x == 0) {
        int i0 = 0; float v0 = sc[0];
        for (int e = 1; e < NUM_E; e++) if (sc[e] > v0) { v0 = sc[e]; i0 = e; }
        int i1 = -1; float v1 = -3.4e38f;
        for (int e = 0; e < NUM_E; e++) if (e != i0 && sc[e] > v1) { v1 = sc[e]; i1 = e; }
        float w0 = 1.f / (1.f + expf(v1 - v0));
        int ev[2] = { i0, i1 };
        float wv[2] = { w0, 1.f - w0 };
        #pragma unroll
        for (int k = 0; k < 2; k++) {
            int e = ev[k];
            int p = atomicAdd(&g_cnt[e], 1);
            if (p < CAP) { g_perm[e*CAP+p] = t; g_slot[t*2+k] = e*CAP+p; g_wgt[t*2+k] = wv[k]; }
            else         { g_slot[t*2+k] = -1; g_wgt[t*2+k] = 0.f; }
        }
    }
}

// ---------------- one 256x64 tile, BK=32, paired stages (R14 inner loop, unchanged) ----------
template<int KD, int ND, bool GATHER, bool GELU_ACT>
__device__ __forceinline__ void process_tile(
    const float* __restrict__ W, const float* __restrict__ bias,
    char* smem, uint32_t sb, int e, int m0, int n0, int cnt)
{
    const int tid = threadIdx.x, lane = tid & 31, wid = tid >> 5;
    const int warpM = wid >> 1, warpN = wid & 1;

    const char* agp[4];
    uint32_t dstA[4];
    #pragma unroll
    for (int p = 0; p < 4; p++) {
        const int rloc = p * 64 + (tid >> 2);
        const int m = m0 + rloc;
        const __nv_bfloat16* rowp;
        if (GATHER) {
            int tok = (m < cnt) ? g_perm[e * CAP + m] : g_perm[e * CAP];
            rowp = g_xb + (size_t)tok * KD;
        } else {
            rowp = g_h + ((size_t)e * CAP + m) * KD;
        }
        agp[p]  = (const char*)rowp + (tid & 3) * 16;
        dstA[p] = SW64_((uint32_t)(rloc * 64 + (tid & 3) * 16));
    }
    const int kr = tid >> 3, ns = tid & 7;
    const float* bsrc = W + ((size_t)e * KD + kr) * ND + n0 + ns * 8;
    const uint32_t dstBF = (uint32_t)(kr * 256 + ns * 32);
    const uint32_t dstBB = SW128_((uint32_t)(kr * 128 + ns * 16));

    float acc[4][4][4];
    #pragma unroll
    for (int i = 0; i < 4; i++)
        #pragma unroll
        for (int j = 0; j < 4; j++)
            #pragma unroll
            for (int q = 0; q < 4; q++) acc[i][j][q] = 0.f;

    auto cpStage = [&](int s) {
        const int b = s & 3;
        const uint32_t aB = sb + OFF_A + b * 16384;
        #pragma unroll
        for (int p = 0; p < 4; p++)
            CP_ASYNC16(aB + dstA[p], agp[p] + s * 64);
        const uint32_t bf = sb + OFF_BF + b * 8192 + dstBF;
        const char* src = (const char*)(bsrc + (size_t)s * BK * ND);
        CP_ASYNC16(bf,      src);
        CP_ASYNC16(bf + 16, src + 16);
    };
    auto convB = [&](int s) {
        const float4* f = reinterpret_cast<const float4*>(smem + OFF_BF + (s & 3) * 8192 + dstBF);
        float4 f0 = f[0], f1 = f[1];
        uint4 v = make_uint4(pk2(f0.x, f0.y), pk2(f0.z, f0.w),
                             pk2(f1.x, f1.y), pk2(f1.z, f1.w));
        *reinterpret_cast<uint4*>(smem + OFF_BB + (s & 3) * 4096 + dstBB) = v;
    };
    auto compute = [&](int s) {
        const uint32_t aB = sb + OFF_A  + (s & 3) * 16384;
        const uint32_t bB = sb + OFF_BB + (s & 3) * 4096;
        #pragma unroll
        for (int kk = 0; kk < 2; kk++) {
            uint32_t af[4][4], bfr[2][4];
            #pragma unroll
            for (int mf = 0; mf < 4; mf++) {
                int row = warpM * 64 + mf * 16 + (lane & 15);
                int seg = kk * 2 + (lane >> 4);
                ldmA(af[mf], aB + SW64_(row * 64 + seg * 16));
            }
            #pragma unroll
            for (int np = 0; np < 2; np++) {
                int krow = kk * 16 + (lane & 15);
                int nc   = warpN * 32 + np * 16 + ((lane >> 4) & 1) * 8;
                ldmBT(bfr[np], bB + SW128_(krow * 128 + nc * 2));
            }
            #pragma unroll
            for (int mf = 0; mf < 4; mf++)
                #pragma unroll
                for (int nf = 0; nf < 4; nf++)
                    mma16816(acc[mf][nf], af[mf],
                             bfr[nf >> 1][(nf & 1) * 2], bfr[nf >> 1][(nf & 1) * 2 + 1]);
        }
    };

    const int NS = KD / BK;
    cpStage(0); cpStage(1); CP_COMMIT();
    for (int s = 0; s < NS; s += 2) {
        cp_wait0();
        convB(s);
        convB(s + 1);
        __syncthreads();
        if (s + 2 < NS) { cpStage(s + 2); cpStage(s + 3); CP_COMMIT(); }
        compute(s);
        compute(s + 1);
    }

    const int grp = lane >> 2, tig = lane & 3;
    #pragma unroll
    for (int mf = 0; mf < 4; mf++) {
        const int r0 = m0 + warpM * 64 + mf * 16 + grp;
        #pragma unroll
        for (int nf = 0; nf < 4; nf++) {
            const int col = n0 + warpN * 32 + nf * 8 + 2 * tig;
            const float bv0 = __ldg(&bias[e * ND + col]);
            const float bv1 = __ldg(&bias[e * ND + col + 1]);
            #pragma unroll
            for (int h = 0; h < 2; h++) {
                const int row = r0 + 8 * h;
                float v0 = acc[mf][nf][2 * h + 0] + bv0;
                float v1 = acc[mf][nf][2 * h + 1] + bv1;
                if (GELU_ACT) {
                    v0 = fast_gelu(v0);
                    v1 = fast_gelu(v1);
                    *reinterpret_cast<uint32_t*>(
                        g_h + ((size_t)e * CAP + row) * ND + col) = pk2(v0, v1);
                } else {
                    *reinterpret_cast<float2*>(
                        g_y + ((size_t)e * CAP + row) * ND + col) = make_float2(v0, v1);
                }
            }
        }
    }
}

// ---------------- fused persistent GEMM1+GEMM2, ticket-scheduled ----------------
__global__ __launch_bounds__(256, 2)
void moe_fused(const float* __restrict__ w1, const float* __restrict__ b1,
               const float* __restrict__ w2, const float* __restrict__ b2)
{
    extern __shared__ __align__(1024) char smem[];
    const uint32_t sb = smem_u32(smem);
    const int tid = threadIdx.x;
    __shared__ int s_tile;

    for (;;) {
        if (tid == 0) s_tile = atomicAdd(&g_ticket, 1);
        __syncthreads();
        const int t = s_tile;
        if (t >= NTT) break;

        if (t < NT1) {
            // GEMM1 tile: expert-major so early experts release first
            const int e   = t >> 7;                   // /128
            const int rem = t & 127;
            const int m0  = (rem >> 6) * BM;
            const int n0  = (rem & 63) * BN;
            const int cnt = min(g_cnt[e], CAP);
            if (m0 < cnt)
                process_tile<D_MODEL, D_FF, true, true>(w1, b1, smem, sb, e, m0, n0, cnt);
            __threadfence();
            __syncthreads();
            if (tid == 0) atomicAdd(&g_done[e], 1);
        } else {
            const int t2  = t - NT1;
            const int e   = t2 >> 5;                  // /32
            const int rem = t2 & 31;
            const int m0  = (rem >> 4) * BM;
            const int n0  = (rem & 15) * BN;
            if (tid == 0) {
                while (ld_acq(&g_done[e]) < DONE_TARGET) __nanosleep(128);
            }
            __syncthreads();
            const int cnt = min(g_cnt[e], CAP);
            if (m0 < cnt)
                process_tile<D_FF, D_MODEL, false, false>(w2, b2, smem, sb, e, m0, n0, cnt);
        }
        __syncthreads();   // protect s_tile rewrite next iteration
    }
}

// out[t] = x[t] + w0*y[slot0] + w1*y[slot1]
__global__ void combine_kernel(const float* __restrict__ x, float* __restrict__ out) {
    const int t = blockIdx.x;
    const int s0 = g_slot[t * 2], s1 = g_slot[t * 2 + 1];
    const float w0 = g_wgt[t * 2], w1 = g_wgt[t * 2 + 1];
    const float4* xr = reinterpret_cast<const float4*>(x + (size_t)t * D_MODEL);
    float4* orw = reinterpret_cast<float4*>(out + (size_t)t * D_MODEL);
    const float4* y0 = (s0 >= 0) ? reinterpret_cast<const float4*>(g_y + (size_t)s0 * D_MODEL) : nullptr;
    const float4* y1 = (s1 >= 0) ? reinterpret_cast<const float4*>(g_y + (size_t)s1 * D_MODEL) : nullptr;
    const int i = threadIdx.x;
    float4 rv = xr[i];
    if (y0) { float4 a = y0[i]; rv.x += w0 * a.x; rv.y += w0 * a.y; rv.z += w0 * a.z; rv.w += w0 * a.w; }
    if (y1) { float4 a = y1[i]; rv.x += w1 * a.x; rv.y += w1 * a.y; rv.z += w1 * a.z; rv.w += w1 * a.w; }
    orw[i] = rv;
}

// ---------------- launch ----------------
extern "C" void kernel_launch(void* const* d_in, const int* in_sizes, int n_in,
                              void* d_out, int out_size) {
    const float* x  = (const float*)d_in[0];
    const float* gw = (const float*)d_in[1];
    const float* gb = (const float*)d_in[2];
    const float* w1 = (const float*)d_in[3];
    const float* b1 = (const float*)d_in[4];
    const float* w2 = (const float*)d_in[5];
    const float* b2 = (const float*)d_in[6];
    float* out = (float*)d_out;

    cudaFuncSetAttribute(moe_fused,
                         cudaFuncAttributeMaxDynamicSharedMemorySize, SMEM_DYN);

    zero_kernel<<<1, 32>>>();
    gate_kernel<<<TOKENS, 128>>>(x, gw, gb);
    moe_fused<<<NPERS, 256, SMEM_DYN>>>(w1, b1, w2, b2);
    combine_kernel<<<TOKENS, 256>>>(x, out);
}